// round 1
// baseline (speedup 1.0000x reference)
#include <cuda_runtime.h>
#include <math.h>

#define N_PTS 131072
#define C 128
#define KNUM 27
#define M_MAP 65536
#define EPS 1e-5f

#define BM 64
#define BK 32

// ---- scratch (static device allocations; allowed) ----
__device__ __align__(16) float g_acc[(size_t)N_PTS * C];   // 64 MB accumulator
__device__ __align__(16) float g_y[(size_t)N_PTS * C];     // 64 MB intermediate
__device__ __align__(16) float g_sum[C];
__device__ __align__(16) float g_sq[C];
__device__ __align__(16) float g_scale[C];
__device__ __align__(16) float g_shift[C];

// ---------------------------------------------------------------------------
// Sparse conv: per (block tile of 64 map rows, kernel offset k):
//   contrib[64,128] = x[map_in[k, m0:m0+64]] @ W[k]   (C=128 reduce)
//   atomicAdd into acc[map_out[k, m]][:]
// ---------------------------------------------------------------------------
__global__ __launch_bounds__(256, 4)
void spconv_kernel(const float* __restrict__ x,
                   const float* __restrict__ W,
                   const int* __restrict__ map_in,
                   const int* __restrict__ map_out,
                   float* __restrict__ acc)
{
    __shared__ float As[BK][BM + 1];   // transposed A tile, padded (conflict-free)
    __shared__ float Bs[BK][C];        // B tile

    const int k   = blockIdx.y;
    const int m0  = blockIdx.x * BM;
    const int tid = threadIdx.x;
    const int tx  = tid & 15;          // column group: cols tx*4..+3 and tx*4+64..+67
    const int ty  = tid >> 4;          // row group: rows ty*4..+3

    const int*   mi = map_in  + (size_t)k * M_MAP + m0;
    const int*   mo = map_out + (size_t)k * M_MAP + m0;
    const float* Wk = W + (size_t)k * C * C;

    // gather row indices for the two A-tile loads this thread performs
    const int rowA0 = tid >> 3;            // 0..31
    const int rowA1 = (tid + 256) >> 3;    // 32..63
    const int c4    = tid & 7;             // which float4 within the 32-col slab
    const int gr0 = mi[rowA0];
    const int gr1 = mi[rowA1];

    float accr[4][8];
    #pragma unroll
    for (int i = 0; i < 4; i++)
        #pragma unroll
        for (int j = 0; j < 8; j++) accr[i][j] = 0.0f;

    for (int kk0 = 0; kk0 < C; kk0 += BK) {
        // ---- load A (gathered), store transposed ----
        {
            float4 v0 = *(const float4*)(x + (size_t)gr0 * C + kk0 + c4 * 4);
            float4 v1 = *(const float4*)(x + (size_t)gr1 * C + kk0 + c4 * 4);
            As[c4 * 4 + 0][rowA0] = v0.x;
            As[c4 * 4 + 1][rowA0] = v0.y;
            As[c4 * 4 + 2][rowA0] = v0.z;
            As[c4 * 4 + 3][rowA0] = v0.w;
            As[c4 * 4 + 0][rowA1] = v1.x;
            As[c4 * 4 + 1][rowA1] = v1.y;
            As[c4 * 4 + 2][rowA1] = v1.z;
            As[c4 * 4 + 3][rowA1] = v1.w;
        }
        // ---- load B: rows kk0..kk0+31, all 128 cols (contiguous) ----
        #pragma unroll
        for (int i = 0; i < 4; i++) {
            int l   = tid + i * 256;
            int row = l >> 5;          // 0..31
            int cc  = l & 31;          // float4 index in row
            *(float4*)&Bs[row][cc * 4] =
                *(const float4*)(Wk + (size_t)(kk0 + row) * C + cc * 4);
        }
        __syncthreads();

        // ---- FMA microkernel ----
        #pragma unroll
        for (int kk = 0; kk < BK; kk++) {
            float a0 = As[kk][ty * 4 + 0];
            float a1 = As[kk][ty * 4 + 1];
            float a2 = As[kk][ty * 4 + 2];
            float a3 = As[kk][ty * 4 + 3];
            float4 b0 = *(const float4*)&Bs[kk][tx * 4];
            float4 b1 = *(const float4*)&Bs[kk][tx * 4 + 64];
            float bb[8] = {b0.x, b0.y, b0.z, b0.w, b1.x, b1.y, b1.z, b1.w};
            #pragma unroll
            for (int j = 0; j < 8; j++) {
                accr[0][j] = fmaf(a0, bb[j], accr[0][j]);
                accr[1][j] = fmaf(a1, bb[j], accr[1][j]);
                accr[2][j] = fmaf(a2, bb[j], accr[2][j]);
                accr[3][j] = fmaf(a3, bb[j], accr[3][j]);
            }
        }
        __syncthreads();
    }

    // ---- scatter-add ----
    #pragma unroll
    for (int i = 0; i < 4; i++) {
        int ro = mo[ty * 4 + i];
        float* dst = acc + (size_t)ro * C;
        #pragma unroll
        for (int j = 0; j < 4; j++) {
            atomicAdd(dst + tx * 4 + j,      accr[i][j]);
            atomicAdd(dst + tx * 4 + 64 + j, accr[i][j + 4]);
        }
    }
}

// ---------------------------------------------------------------------------
// BN stats: per-channel sum & sum-of-squares over N rows.
// ---------------------------------------------------------------------------
__global__ void zero_stats_kernel()
{
    int c = threadIdx.x;
    g_sum[c] = 0.0f;
    g_sq[c]  = 0.0f;
}

__global__ __launch_bounds__(256)
void bn_stats_kernel(const float* __restrict__ a)
{
    __shared__ float ss[256];
    __shared__ float sq[256];
    const int tid = threadIdx.x;
    const int c   = tid & 127;
    const int sub = tid >> 7;   // 0/1

    float s = 0.0f, q = 0.0f;
    for (int r = blockIdx.x * 2 + sub; r < N_PTS; r += gridDim.x * 2) {
        float v = a[(size_t)r * C + c];
        s += v;
        q += v * v;
    }
    ss[tid] = s;
    sq[tid] = q;
    __syncthreads();
    if (tid < 128) {
        atomicAdd(&g_sum[c], ss[tid] + ss[tid + 128]);
        atomicAdd(&g_sq[c],  sq[tid] + sq[tid + 128]);
    }
}

__global__ void bn_finalize_kernel(const float* __restrict__ gamma,
                                   const float* __restrict__ beta)
{
    int c = threadIdx.x;
    float m  = g_sum[c] * (1.0f / N_PTS);
    float v  = g_sq[c] * (1.0f / N_PTS) - m * m;
    float is = rsqrtf(v + EPS);
    float sc = is * gamma[c];
    g_scale[c] = sc;
    g_shift[c] = beta[c] - m * sc;
}

// ---------------------------------------------------------------------------
// Apply kernels (vectorized float4)
// ---------------------------------------------------------------------------
__device__ __forceinline__ float elu_f(float x)
{
    return x > 0.0f ? x : expm1f(x);
}

__global__ __launch_bounds__(256)
void apply_bn_elu_kernel(const float* __restrict__ a, float* __restrict__ o)
{
    int idx = blockIdx.x * blockDim.x + threadIdx.x;   // float4 index
    int c4  = idx & 31;                                // 32 float4 per row
    float4 v  = ((const float4*)a)[idx];
    float4 sc = ((const float4*)g_scale)[c4];
    float4 sh = ((const float4*)g_shift)[c4];
    float4 r;
    r.x = elu_f(fmaf(v.x, sc.x, sh.x));
    r.y = elu_f(fmaf(v.y, sc.y, sh.y));
    r.z = elu_f(fmaf(v.z, sc.z, sh.z));
    r.w = elu_f(fmaf(v.w, sc.w, sh.w));
    ((float4*)o)[idx] = r;
}

__global__ __launch_bounds__(256)
void apply_bn_res_elu_kernel(const float* __restrict__ a,
                             const float* __restrict__ resid,
                             float* __restrict__ o)
{
    int idx = blockIdx.x * blockDim.x + threadIdx.x;
    int c4  = idx & 31;
    float4 v  = ((const float4*)a)[idx];
    float4 rs = ((const float4*)resid)[idx];
    float4 sc = ((const float4*)g_scale)[c4];
    float4 sh = ((const float4*)g_shift)[c4];
    float4 r;
    r.x = elu_f(fmaf(v.x, sc.x, sh.x) + rs.x);
    r.y = elu_f(fmaf(v.y, sc.y, sh.y) + rs.y);
    r.z = elu_f(fmaf(v.z, sc.z, sh.z) + rs.z);
    r.w = elu_f(fmaf(v.w, sc.w, sh.w) + rs.w);
    ((float4*)o)[idx] = r;
}

// ---------------------------------------------------------------------------
// Launch
// ---------------------------------------------------------------------------
extern "C" void kernel_launch(void* const* d_in, const int* in_sizes, int n_in,
                              void* d_out, int out_size)
{
    const float* x       = (const float*)d_in[0];
    const float* W1      = (const float*)d_in[1];
    const float* gamma1  = (const float*)d_in[2];
    const float* beta1   = (const float*)d_in[3];
    const float* W2      = (const float*)d_in[4];
    const float* gamma2  = (const float*)d_in[5];
    const float* beta2   = (const float*)d_in[6];
    const int*   map1_in  = (const int*)d_in[7];
    const int*   map1_out = (const int*)d_in[8];
    const int*   map2_in  = (const int*)d_in[9];
    const int*   map2_out = (const int*)d_in[10];
    float* out = (float*)d_out;

    void* accPtr = nullptr;
    void* yPtr   = nullptr;
    cudaGetSymbolAddress(&accPtr, g_acc);
    cudaGetSymbolAddress(&yPtr, g_y);
    const size_t accBytes = (size_t)N_PTS * C * sizeof(float);

    const dim3 convGrid(M_MAP / BM, KNUM);
    const int  elem4   = (N_PTS * C) / 4;
    const int  ewGrid  = elem4 / 256;

    // ---- layer 1 ----
    cudaMemsetAsync(accPtr, 0, accBytes);
    zero_stats_kernel<<<1, C>>>();
    spconv_kernel<<<convGrid, 256>>>(x, W1, map1_in, map1_out, (float*)accPtr);
    bn_stats_kernel<<<256, 256>>>((const float*)accPtr);
    bn_finalize_kernel<<<1, C>>>(gamma1, beta1);
    apply_bn_elu_kernel<<<ewGrid, 256>>>((const float*)accPtr, (float*)yPtr);

    // ---- layer 2 ----
    cudaMemsetAsync(accPtr, 0, accBytes);
    zero_stats_kernel<<<1, C>>>();
    spconv_kernel<<<convGrid, 256>>>((const float*)yPtr, W2, map2_in, map2_out,
                                     (float*)accPtr);
    bn_stats_kernel<<<256, 256>>>((const float*)accPtr);
    bn_finalize_kernel<<<1, C>>>(gamma2, beta2);
    apply_bn_res_elu_kernel<<<ewGrid, 256>>>((const float*)accPtr, x, out);
}

// round 2
// speedup vs baseline: 1.0017x; 1.0017x over previous
#include <cuda_runtime.h>
#include <math.h>

#define N_PTS 131072
#define C 128
#define KNUM 27
#define M_MAP 65536
#define EPS 1e-5f

#define BM 64
#define BK 32

// ---- scratch (static device allocations; allowed) ----
__device__ __align__(16) float g_acc[(size_t)N_PTS * C];   // 64 MB accumulator
__device__ __align__(16) float g_y[(size_t)N_PTS * C];     // 64 MB intermediate
__device__ __align__(16) float g_sum[C];
__device__ __align__(16) float g_sq[C];
__device__ __align__(16) float g_scale[C];
__device__ __align__(16) float g_shift[C];

// ---------------------------------------------------------------------------
// Sparse conv: per (block tile of 64 map rows, kernel offset k):
//   contrib[64,128] = x[map_in[k, m0:m0+64]] @ W[k]   (C=128 reduce)
//   atomicAdd into acc[map_out[k, m]][:]
// ---------------------------------------------------------------------------
__global__ __launch_bounds__(256, 4)
void spconv_kernel(const float* __restrict__ x,
                   const float* __restrict__ W,
                   const int* __restrict__ map_in,
                   const int* __restrict__ map_out,
                   float* __restrict__ acc)
{
    __shared__ float As[BK][BM + 1];   // transposed A tile, padded (conflict-free)
    __shared__ float Bs[BK][C];        // B tile

    const int k   = blockIdx.y;
    const int m0  = blockIdx.x * BM;
    const int tid = threadIdx.x;
    const int tx  = tid & 15;          // column group: cols tx*4..+3 and tx*4+64..+67
    const int ty  = tid >> 4;          // row group: rows ty*4..+3

    const int*   mi = map_in  + (size_t)k * M_MAP + m0;
    const int*   mo = map_out + (size_t)k * M_MAP + m0;
    const float* Wk = W + (size_t)k * C * C;

    // gather row indices for the two A-tile loads this thread performs
    const int rowA0 = tid >> 3;            // 0..31
    const int rowA1 = (tid + 256) >> 3;    // 32..63
    const int c4    = tid & 7;             // which float4 within the 32-col slab
    const int gr0 = mi[rowA0];
    const int gr1 = mi[rowA1];

    float accr[4][8];
    #pragma unroll
    for (int i = 0; i < 4; i++)
        #pragma unroll
        for (int j = 0; j < 8; j++) accr[i][j] = 0.0f;

    for (int kk0 = 0; kk0 < C; kk0 += BK) {
        // ---- load A (gathered), store transposed ----
        {
            float4 v0 = *(const float4*)(x + (size_t)gr0 * C + kk0 + c4 * 4);
            float4 v1 = *(const float4*)(x + (size_t)gr1 * C + kk0 + c4 * 4);
            As[c4 * 4 + 0][rowA0] = v0.x;
            As[c4 * 4 + 1][rowA0] = v0.y;
            As[c4 * 4 + 2][rowA0] = v0.z;
            As[c4 * 4 + 3][rowA0] = v0.w;
            As[c4 * 4 + 0][rowA1] = v1.x;
            As[c4 * 4 + 1][rowA1] = v1.y;
            As[c4 * 4 + 2][rowA1] = v1.z;
            As[c4 * 4 + 3][rowA1] = v1.w;
        }
        // ---- load B: rows kk0..kk0+31, all 128 cols (contiguous) ----
        #pragma unroll
        for (int i = 0; i < 4; i++) {
            int l   = tid + i * 256;
            int row = l >> 5;          // 0..31
            int cc  = l & 31;          // float4 index in row
            *(float4*)&Bs[row][cc * 4] =
                *(const float4*)(Wk + (size_t)(kk0 + row) * C + cc * 4);
        }
        __syncthreads();

        // ---- FMA microkernel ----
        #pragma unroll
        for (int kk = 0; kk < BK; kk++) {
            float a0 = As[kk][ty * 4 + 0];
            float a1 = As[kk][ty * 4 + 1];
            float a2 = As[kk][ty * 4 + 2];
            float a3 = As[kk][ty * 4 + 3];
            float4 b0 = *(const float4*)&Bs[kk][tx * 4];
            float4 b1 = *(const float4*)&Bs[kk][tx * 4 + 64];
            float bb[8] = {b0.x, b0.y, b0.z, b0.w, b1.x, b1.y, b1.z, b1.w};
            #pragma unroll
            for (int j = 0; j < 8; j++) {
                accr[0][j] = fmaf(a0, bb[j], accr[0][j]);
                accr[1][j] = fmaf(a1, bb[j], accr[1][j]);
                accr[2][j] = fmaf(a2, bb[j], accr[2][j]);
                accr[3][j] = fmaf(a3, bb[j], accr[3][j]);
            }
        }
        __syncthreads();
    }

    // ---- scatter-add ----
    #pragma unroll
    for (int i = 0; i < 4; i++) {
        int ro = mo[ty * 4 + i];
        float* dst = acc + (size_t)ro * C;
        #pragma unroll
        for (int j = 0; j < 4; j++) {
            atomicAdd(dst + tx * 4 + j,      accr[i][j]);
            atomicAdd(dst + tx * 4 + 64 + j, accr[i][j + 4]);
        }
    }
}

// ---------------------------------------------------------------------------
// BN stats: per-channel sum & sum-of-squares over N rows.
// ---------------------------------------------------------------------------
__global__ void zero_stats_kernel()
{
    int c = threadIdx.x;
    g_sum[c] = 0.0f;
    g_sq[c]  = 0.0f;
}

__global__ __launch_bounds__(256)
void bn_stats_kernel(const float* __restrict__ a)
{
    __shared__ float ss[256];
    __shared__ float sq[256];
    const int tid = threadIdx.x;
    const int c   = tid & 127;
    const int sub = tid >> 7;   // 0/1

    float s = 0.0f, q = 0.0f;
    for (int r = blockIdx.x * 2 + sub; r < N_PTS; r += gridDim.x * 2) {
        float v = a[(size_t)r * C + c];
        s += v;
        q += v * v;
    }
    ss[tid] = s;
    sq[tid] = q;
    __syncthreads();
    if (tid < 128) {
        atomicAdd(&g_sum[c], ss[tid] + ss[tid + 128]);
        atomicAdd(&g_sq[c],  sq[tid] + sq[tid + 128]);
    }
}

__global__ void bn_finalize_kernel(const float* __restrict__ gamma,
                                   const float* __restrict__ beta)
{
    int c = threadIdx.x;
    float m  = g_sum[c] * (1.0f / N_PTS);
    float v  = g_sq[c] * (1.0f / N_PTS) - m * m;
    float is = rsqrtf(v + EPS);
    float sc = is * gamma[c];
    g_scale[c] = sc;
    g_shift[c] = beta[c] - m * sc;
}

// ---------------------------------------------------------------------------
// Apply kernels (vectorized float4)
// ---------------------------------------------------------------------------
__device__ __forceinline__ float elu_f(float x)
{
    return x > 0.0f ? x : expm1f(x);
}

__global__ __launch_bounds__(256)
void apply_bn_elu_kernel(const float* __restrict__ a, float* __restrict__ o)
{
    int idx = blockIdx.x * blockDim.x + threadIdx.x;   // float4 index
    int c4  = idx & 31;                                // 32 float4 per row
    float4 v  = ((const float4*)a)[idx];
    float4 sc = ((const float4*)g_scale)[c4];
    float4 sh = ((const float4*)g_shift)[c4];
    float4 r;
    r.x = elu_f(fmaf(v.x, sc.x, sh.x));
    r.y = elu_f(fmaf(v.y, sc.y, sh.y));
    r.z = elu_f(fmaf(v.z, sc.z, sh.z));
    r.w = elu_f(fmaf(v.w, sc.w, sh.w));
    ((float4*)o)[idx] = r;
}

__global__ __launch_bounds__(256)
void apply_bn_res_elu_kernel(const float* __restrict__ a,
                             const float* __restrict__ resid,
                             float* __restrict__ o)
{
    int idx = blockIdx.x * blockDim.x + threadIdx.x;
    int c4  = idx & 31;
    float4 v  = ((const float4*)a)[idx];
    float4 rs = ((const float4*)resid)[idx];
    float4 sc = ((const float4*)g_scale)[c4];
    float4 sh = ((const float4*)g_shift)[c4];
    float4 r;
    r.x = elu_f(fmaf(v.x, sc.x, sh.x) + rs.x);
    r.y = elu_f(fmaf(v.y, sc.y, sh.y) + rs.y);
    r.z = elu_f(fmaf(v.z, sc.z, sh.z) + rs.z);
    r.w = elu_f(fmaf(v.w, sc.w, sh.w) + rs.w);
    ((float4*)o)[idx] = r;
}

// ---------------------------------------------------------------------------
// Launch
// ---------------------------------------------------------------------------
extern "C" void kernel_launch(void* const* d_in, const int* in_sizes, int n_in,
                              void* d_out, int out_size)
{
    const float* x       = (const float*)d_in[0];
    const float* W1      = (const float*)d_in[1];
    const float* gamma1  = (const float*)d_in[2];
    const float* beta1   = (const float*)d_in[3];
    const float* W2      = (const float*)d_in[4];
    const float* gamma2  = (const float*)d_in[5];
    const float* beta2   = (const float*)d_in[6];
    const int*   map1_in  = (const int*)d_in[7];
    const int*   map1_out = (const int*)d_in[8];
    const int*   map2_in  = (const int*)d_in[9];
    const int*   map2_out = (const int*)d_in[10];
    float* out = (float*)d_out;

    void* accPtr = nullptr;
    void* yPtr   = nullptr;
    cudaGetSymbolAddress(&accPtr, g_acc);
    cudaGetSymbolAddress(&yPtr, g_y);
    const size_t accBytes = (size_t)N_PTS * C * sizeof(float);

    const dim3 convGrid(M_MAP / BM, KNUM);
    const int  elem4   = (N_PTS * C) / 4;
    const int  ewGrid  = elem4 / 256;

    // ---- layer 1 ----
    cudaMemsetAsync(accPtr, 0, accBytes);
    zero_stats_kernel<<<1, C>>>();
    spconv_kernel<<<convGrid, 256>>>(x, W1, map1_in, map1_out, (float*)accPtr);
    bn_stats_kernel<<<256, 256>>>((const float*)accPtr);
    bn_finalize_kernel<<<1, C>>>(gamma1, beta1);
    apply_bn_elu_kernel<<<ewGrid, 256>>>((const float*)accPtr, (float*)yPtr);

    // ---- layer 2 ----
    cudaMemsetAsync(accPtr, 0, accBytes);
    zero_stats_kernel<<<1, C>>>();
    spconv_kernel<<<convGrid, 256>>>((const float*)yPtr, W2, map2_in, map2_out,
                                     (float*)accPtr);
    bn_stats_kernel<<<256, 256>>>((const float*)accPtr);
    bn_finalize_kernel<<<1, C>>>(gamma2, beta2);
    apply_bn_res_elu_kernel<<<ewGrid, 256>>>((const float*)accPtr, x, out);
}